// round 7
// baseline (speedup 1.0000x reference)
#include <cuda_runtime.h>

// Equivariant linear: RS = [(16,0),(16,1),(16,2)], dim = 144, BATCH = 262144.
// Block-diagonal per (l,m): out[z,l,v,t] = sum_u Wl[v,u] * x[z,l,u,t],
// Wl[v,u] = weight[l*256 + v*16 + u] * 0.25 / sqrt(2l+1).
// Row layout: l=0 cols [0,16) d=1; l=1 idx 16+u*3+t; l=2 idx 64+u*5+t.
//
// R7: persistent grid (152 SMs x 2 CTAs), double-buffered 64-row tiles,
// cp.async global->smem prefetch overlapped with compute+store.

#define ROWS 64
#define STRIDE 145      // odd -> row-axis scalar gather conflict-free
#define NT 288          // 9 warps = 9 m-slices
#define DIM 144
#define EPT 32          // 64*144 / 288 staged elements per thread
#define NTILES 4096     // 262144 / 64
#define NBLOCKS 304     // 152 SMs * 2 CTAs (smem-limited occupancy)

#define SMEM_FLOATS (768 + 2 * ROWS * STRIDE)
#define SMEM_BYTES  (SMEM_FLOATS * 4)

typedef unsigned long long ull;

__device__ __forceinline__ ull pack_dup(float x) {
    ull r;
    asm("mov.b64 %0, {%1, %1};" : "=l"(r) : "f"(x));
    return r;
}
__device__ __forceinline__ void ffma2(ull& acc, ull w2, ull x2) {
    asm("fma.rn.f32x2 %0, %1, %2, %0;" : "+l"(acc) : "l"(w2), "l"(x2));
}
__device__ __forceinline__ void unpack2(ull p, float& lo, float& hi) {
    asm("mov.b64 {%0, %1}, %2;" : "=f"(lo), "=f"(hi) : "l"(p));
}
__device__ __forceinline__ void cp4(unsigned sdst, const float* gsrc) {
    asm volatile("cp.async.ca.shared.global [%0], [%1], 4;"
                 :: "r"(sdst), "l"(gsrc));
}

__global__ __launch_bounds__(NT) void eq_linear_kernel(
    const float* __restrict__ x,
    const float* __restrict__ w,
    float* __restrict__ y)
{
    extern __shared__ __align__(16) float dyn[];
    float* sWT = dyn;                 // 768 floats: WT[l][u][v], pre-scaled
    float* sD0 = dyn + 768;           // buffer 0: 64 x 145
    float* sD1 = sD0 + ROWS * STRIDE; // buffer 1

    const int tid  = threadIdx.x;
    const int lane = tid & 31;
    const int s    = tid >> 5;        // warp id == slice id, 0..8

    // Stage transposed, pre-scaled mixing matrices:
    // sWT[l*256 + u*16 + v] = weight[l*256 + v*16 + u] * 0.25/sqrt(2l+1)
    for (int i = tid; i < 768; i += NT) {
        int l = i >> 8;
        int rem = i & 255;
        int u = rem >> 4;
        int v = rem & 15;
        float scale = (l == 0) ? 0.25f
                    : (l == 1) ? 0.25f * 0.57735026918962576f   // 1/sqrt(3)
                               : 0.25f * 0.44721359549995794f;  // 1/sqrt(5)
        sWT[i] = w[l * 256 + v * 16 + u] * scale;
    }

    // Per-thread staging coordinates: column c, base row rb, rows rb+2k.
    const int c  = tid % DIM;
    const int rb = tid / DIM;         // 0 or 1
    const unsigned sOff = (unsigned)((rb * STRIDE + c) * 4);
    const unsigned sBase0 = (unsigned)__cvta_generic_to_shared(sD0) + sOff;
    const unsigned sBase1 = (unsigned)__cvta_generic_to_shared(sD1) + sOff;

    // Slice geometry for this warp.
    int l, off, d;
    if (s == 0)      { l = 0; off = 0;            d = 1; }
    else if (s < 4)  { l = 1; off = 16 + (s - 1); d = 3; }
    else             { l = 2; off = 64 + (s - 4); d = 5; }
    const ulonglong2* __restrict__ WT =
        reinterpret_cast<const ulonglong2*>(sWT + l * 256);

    // Prologue: prefetch first tile into buffer 0.
    {
        const float* gsrc = x + ((long long)blockIdx.x * ROWS + rb) * DIM + c;
        #pragma unroll
        for (int k = 0; k < EPT; k++)
            cp4(sBase0 + (unsigned)(2 * k) * (STRIDE * 4),
                gsrc + (long long)(2 * k) * DIM);
        asm volatile("cp.async.commit_group;");
    }

    int it = 0;
    for (int t = blockIdx.x; t < NTILES; t += NBLOCKS, it++) {
        const int buf = it & 1;
        float* sD = buf ? sD1 : sD0;
        const int tn = t + NBLOCKS;

        // Prefetch next tile into the other buffer, then wait for tile t.
        if (tn < NTILES) {
            const unsigned nb = buf ? sBase0 : sBase1;
            const float* gsrc = x + ((long long)tn * ROWS + rb) * DIM + c;
            #pragma unroll
            for (int k = 0; k < EPT; k++)
                cp4(nb + (unsigned)(2 * k) * (STRIDE * 4),
                    gsrc + (long long)(2 * k) * DIM);
            asm volatile("cp.async.commit_group;");
            asm volatile("cp.async.wait_group 1;");
        } else {
            asm volatile("cp.async.wait_group 0;");
        }
        __syncthreads();

        // Compute: warp s owns slice s; lane owns rows {lane, lane+32}.
        {
            float* p0 = sD + lane * STRIDE + off;
            float* p1 = p0 + 32 * STRIDE;

            ull a0[8], a1[8];
            #pragma unroll
            for (int j = 0; j < 8; j++) { a0[j] = 0ull; a1[j] = 0ull; }

            #pragma unroll
            for (int u = 0; u < 16; u++) {
                ull xd0 = pack_dup(p0[u * d]);     // conflict-free scalar LDS
                ull xd1 = pack_dup(p1[u * d]);
                #pragma unroll
                for (int q = 0; q < 4; q++) {
                    ulonglong2 wp = WT[u * 4 + q]; // warp-uniform LDS.128
                    ffma2(a0[2*q+0], wp.x, xd0);
                    ffma2(a0[2*q+1], wp.y, xd0);
                    ffma2(a1[2*q+0], wp.x, xd1);
                    ffma2(a1[2*q+1], wp.y, xd1);
                }
            }

            #pragma unroll
            for (int j = 0; j < 8; j++) {
                float lo, hi;
                unpack2(a0[j], lo, hi);
                p0[(2*j+0) * d] = lo;
                p0[(2*j+1) * d] = hi;
                unpack2(a1[j], lo, hi);
                p1[(2*j+0) * d] = lo;
                p1[(2*j+1) * d] = hi;
            }
        }
        __syncthreads();

        // Coalesced scalar store of tile t.
        {
            float* __restrict__ gdst = y + ((long long)t * ROWS + rb) * DIM + c;
            const float* sdst = sD + rb * STRIDE + c;
            #pragma unroll 8
            for (int k = 0; k < EPT; k++)
                gdst[(long long)(2 * k) * DIM] = sdst[(2 * k) * STRIDE];
        }
        // Guard: next iteration's cp.async targets this buffer only after
        // every warp has finished reading it above.
        __syncthreads();
    }
}

extern "C" void kernel_launch(void* const* d_in, const int* in_sizes, int n_in,
                              void* d_out, int out_size)
{
    const float* feat = (const float*)d_in[0];
    const float* w    = (const float*)d_in[1];
    float* out        = (float*)d_out;

    cudaFuncSetAttribute(eq_linear_kernel,
                         cudaFuncAttributeMaxDynamicSharedMemorySize,
                         SMEM_BYTES);

    eq_linear_kernel<<<NBLOCKS, NT, SMEM_BYTES>>>(feat, w, out);
}

// round 8
// speedup vs baseline: 1.0480x; 1.0480x over previous
#include <cuda_runtime.h>

// Equivariant linear: RS = [(16,0),(16,1),(16,2)], dim = 144, BATCH = 262144.
// Block-diagonal per (l,m): out[z,l,v,t] = sum_u Wl[v,u] * x[z,l,u,t],
// Wl[v,u] = weight[l*256 + v*16 + u] * 0.25 / sqrt(2l+1).
// Row layout: l=0 cols [0,16) d=1; l=1 idx 16+u*3+t; l=2 idx 64+u*5+t.
//
// R8: 32-row one-shot tiles, 288 thr (9 warps = 9 slices), 1 row/thread
// compute with f32x2, scalar coalesced staging, 56-reg cap -> 4 CTAs/SM.

#define ROWS 32
#define STRIDE 145      // odd -> row-axis scalar gather/scatter conflict-free
#define NT 288          // 9 warps = 9 m-slices
#define DIM 144
#define EPT 16          // 32*144 / 288 staged elements per thread

typedef unsigned long long ull;

__device__ __forceinline__ ull pack_dup(float x) {
    ull r;
    asm("mov.b64 %0, {%1, %1};" : "=l"(r) : "f"(x));
    return r;
}
__device__ __forceinline__ void ffma2(ull& acc, ull w2, ull x2) {
    asm("fma.rn.f32x2 %0, %1, %2, %0;" : "+l"(acc) : "l"(w2), "l"(x2));
}
__device__ __forceinline__ void unpack2(ull p, float& lo, float& hi) {
    asm("mov.b64 {%0, %1}, %2;" : "=f"(lo), "=f"(hi) : "l"(p));
}

__global__ __launch_bounds__(NT, 4) void eq_linear_kernel(
    const float* __restrict__ x,
    const float* __restrict__ w,
    float* __restrict__ y)
{
    __shared__ __align__(16) float sWT[768];   // WT[l][u][v], pre-scaled
    __shared__ float sD[ROWS * STRIDE];

    const int tid  = threadIdx.x;
    const int lane = tid & 31;
    const int s    = tid >> 5;      // warp id == slice id, 0..8

    // Stage transposed, pre-scaled mixing matrices:
    // sWT[l*256 + u*16 + v] = weight[l*256 + v*16 + u] * 0.25/sqrt(2l+1)
    for (int i = tid; i < 768; i += NT) {
        int l = i >> 8;
        int rem = i & 255;
        int u = rem >> 4;
        int v = rem & 15;
        float scale = (l == 0) ? 0.25f
                    : (l == 1) ? 0.25f * 0.57735026918962576f   // 1/sqrt(3)
                               : 0.25f * 0.44721359549995794f;  // 1/sqrt(5)
        sWT[i] = w[l * 256 + v * 16 + u] * scale;
    }

    const long long row0 = (long long)blockIdx.x * ROWS;

    // Coalesced scalar tile load: thread owns column c = tid % 144,
    // rows rb + 2k. Consecutive lanes -> consecutive addresses (1 wf/instr);
    // STS conflict-free likewise.
    const int c  = tid % DIM;
    const int rb = tid / DIM;               // 0 or 1
    {
        const float* __restrict__ gsrc = x + (row0 + rb) * DIM + c;
        float* ssrc = sD + rb * STRIDE + c;
        #pragma unroll
        for (int k = 0; k < EPT; k++)
            ssrc[(2 * k) * STRIDE] = gsrc[(long long)(2 * k) * DIM];
    }
    __syncthreads();

    // Compute: warp s owns slice s; lane owns row lane.
    // v-pair-packed f32x2 FMAs: acc{2j,2j+1} += {w_2j, w_2j+1} * {x, x}.
    {
        int l, off, d;
        if (s == 0)      { l = 0; off = 0;            d = 1; }
        else if (s < 4)  { l = 1; off = 16 + (s - 1); d = 3; }
        else             { l = 2; off = 64 + (s - 4); d = 5; }

        float* p = sD + lane * STRIDE + off;
        const ulonglong2* __restrict__ WT =
            reinterpret_cast<const ulonglong2*>(sWT + l * 256);

        ull a[8];
        #pragma unroll
        for (int j = 0; j < 8; j++) a[j] = 0ull;

        #pragma unroll
        for (int u = 0; u < 16; u++) {
            ull xd = pack_dup(p[u * d]);       // conflict-free scalar LDS
            #pragma unroll
            for (int q = 0; q < 4; q++) {
                ulonglong2 wp = WT[u * 4 + q]; // warp-uniform LDS.128 = 4 w's
                ffma2(a[2*q+0], wp.x, xd);
                ffma2(a[2*q+1], wp.y, xd);
            }
        }

        #pragma unroll
        for (int j = 0; j < 8; j++) {
            float lo, hi;
            unpack2(a[j], lo, hi);
            p[(2*j+0) * d] = lo;
            p[(2*j+1) * d] = hi;
        }
    }
    __syncthreads();

    // Coalesced scalar store (mirror of the load).
    {
        float* __restrict__ gdst = y + (row0 + rb) * DIM + c;
        const float* sdst = sD + rb * STRIDE + c;
        #pragma unroll
        for (int k = 0; k < EPT; k++)
            gdst[(long long)(2 * k) * DIM] = sdst[(2 * k) * STRIDE];
    }
}

extern "C" void kernel_launch(void* const* d_in, const int* in_sizes, int n_in,
                              void* d_out, int out_size)
{
    const float* feat = (const float*)d_in[0];
    const float* w    = (const float*)d_in[1];
    float* out        = (float*)d_out;

    const int batch  = in_sizes[0] / DIM;   // 262144
    const int blocks = batch / ROWS;        // 8192

    eq_linear_kernel<<<blocks, NT>>>(feat, w, out);
}